// round 14
// baseline (speedup 1.0000x reference)
#include <cuda_runtime.h>
#include <cstddef>

// Problem: B=64, n_l=512, n_h=32, d_l=16, d_h=32
#define Bsz 64
#define NLc 512
#define NHc 32
#define DLc 16
#define KLc 1024   // NH*DH
#define INV_SCALE 0.17677669529663687f  // 1/sqrt(32)
#define FNI 16     // i's per CTA chunk

// Static scratch (zero-initialized at module load; k_squash re-zeros after use,
// so the "zeroed at entry" invariant is self-restoring across calls/replays).
__device__ float g_S[Bsz * KLc];          // S[b][k*32+l]
__device__ float g_Uh[Bsz * KLc];         // U_h accumulator

// Packed fp32x2 FMA (sm_100+)
__device__ __forceinline__ float2 ffma2(float2 a, float2 b, float2 c) {
    float2 d;
    asm("{\n\t"
        ".reg .b64 ra, rb, rc, rd;\n\t"
        "mov.b64 ra, {%2, %3};\n\t"
        "mov.b64 rb, {%4, %5};\n\t"
        "mov.b64 rc, {%6, %7};\n\t"
        "fma.rn.f32x2 rd, ra, rb, rc;\n\t"
        "mov.b64 {%0, %1}, rd;\n\t"
        "}"
        : "=f"(d.x), "=f"(d.y)
        : "f"(a.x), "f"(a.y), "f"(b.x), "f"(b.y), "f"(c.x), "f"(c.y));
    return d;
}

__device__ __forceinline__ unsigned smem_u32(const void* p) {
    return (unsigned)__cvta_generic_to_shared(p);
}
#define CP_ASYNC16(dst, src) \
    asm volatile("cp.async.ca.shared.global [%0], [%1], 16;" ::"r"(dst), "l"(src))
#define CP_COMMIT() asm volatile("cp.async.commit_group;")
#define CP_WAIT1() asm volatile("cp.async.wait_group 1;" ::: "memory")
#define CP_WAIT0() asm volatile("cp.async.wait_group 0;" ::: "memory")

// U column rotation (fused kernel): conflict-free scalar/vector U reads.
#define UROT(b, j) (((j) + ((b) & 12)) & 15)

// ---------------------------------------------------------------------------
// Pass 1: S[b][k*32+l] = sum_{i,j} U[b,i*16+j] * W[i,k,j,l]
// Grid (4 k-tiles of 8, 32 i-chunks of 16), 256 thr, warp = 1 k.
// Thread tile 8b x 1k x 8l. U in SMEM j-major with quad swizzle ->
// 2 LDS.128 per j load all 8 U values. 64 LDS.128 : 512 ffma2 per iter.
// Pipeline: stage-at-HEAD (commit -> wait -> barrier -> compute), same
// ordering as the proven R12 kernels.
// ---------------------------------------------------------------------------
#define P1W 4096                          // W floats per buffer (8k x 16j x 32l)
#define P1U (16 * 68)                     // U floats per buffer [j][68]
#define P1_FLOATS (2 * P1W + 2 * P1U)
#define P1_BYTES (P1_FLOATS * 4)          // 41472 B

// quad swizzle: quad q (of 16 per row) stored at position q ^ ((q>>3)&1)
__device__ __forceinline__ int usig(int q) { return q ^ ((q >> 3) & 1); }

__device__ __forceinline__ void p1_stage_w(const float* __restrict__ W,
                                           int i, int k0, int tx, float* Ws) {
    const float* Wi = W + (size_t)i * 16384 + (size_t)k0 * 512;
#pragma unroll
    for (int r = 0; r < 4; r++) {
        const int v = tx + r * 256;        // float4 idx 0..1023
        const int k = v >> 7, j = (v >> 3) & 15, lq = v & 7;
        CP_ASYNC16(smem_u32(Ws + j * 256 + k * 32 + lq * 4),
                   Wi + (size_t)k * 512 + j * 32 + lq * 4);
    }
}

__global__ void __launch_bounds__(256, 2) k_pass1(const float* __restrict__ U,
                                                  const float* __restrict__ W) {
    extern __shared__ float sm[];
    float* Wsb[2] = {sm, sm + P1W};
    float* Usb[2] = {sm + 2 * P1W, sm + 2 * P1W + P1U};

    const int tx = threadIdx.x;
    const int w = tx >> 5;               // local k
    const int lane = tx & 31;
    const int bg = lane >> 2;            // 8 b-groups of 8 b
    const int lg = lane & 3;             // l quad group
    const int k0 = blockIdx.x * 8;
    const int i0 = blockIdx.y * FNI;
    const int wc0 = w * 32 + lg * 4;     // W chunk e=0 (float offset in j-row)
    const int wc1 = wc0 + 16;            // e=1
    const int uo0 = usig(2 * bg) * 4;    // U chunk offsets within j-row
    const int uo1 = usig(2 * bg + 1) * 4;

    // U loader mapping (LDG->STS staging): (lb, lj4) unique over 256 threads
    const int lb = (tx & 7) + (tx >> 5) * 8;        // b 0..63
    const int lj4 = ((tx >> 3) & 3) * 4;            // j4 in {0,4,8,12}
    const int lsig = usig(lb >> 2) * 4 + (lb & 3);  // storage float offset in row

    float2 acc[8][4];
#pragma unroll
    for (int bb = 0; bb < 8; bb++)
#pragma unroll
        for (int p = 0; p < 4; p++) acc[bb][p] = make_float2(0.f, 0.f);

    // prologue: W(i0) via cp.async; U(i0) direct LDG->STS; prefetch U(i0+1)
    p1_stage_w(W, i0, k0, tx, Wsb[0]);
    CP_COMMIT();
    {
        const float4 u0 = *reinterpret_cast<const float4*>(
            U + (size_t)lb * 8192 + (size_t)i0 * 16 + lj4);
        Usb[0][(lj4 + 0) * 68 + lsig] = u0.x;
        Usb[0][(lj4 + 1) * 68 + lsig] = u0.y;
        Usb[0][(lj4 + 2) * 68 + lsig] = u0.z;
        Usb[0][(lj4 + 3) * 68 + lsig] = u0.w;
    }
    float4 ureg = *reinterpret_cast<const float4*>(
        U + (size_t)lb * 8192 + (size_t)(i0 + 1) * 16 + lj4);

    int s = 0;
    for (int it = 0; it < FNI; it++) {
        // stage next buffer (head of iteration, proven ordering)
        if (it + 1 < FNI) {
            p1_stage_w(W, i0 + it + 1, k0, tx, Wsb[s ^ 1]);
            CP_COMMIT();
            float* Un = Usb[s ^ 1];
            Un[(lj4 + 0) * 68 + lsig] = ureg.x;
            Un[(lj4 + 1) * 68 + lsig] = ureg.y;
            Un[(lj4 + 2) * 68 + lsig] = ureg.z;
            Un[(lj4 + 3) * 68 + lsig] = ureg.w;
            if (it + 2 < FNI)
                ureg = *reinterpret_cast<const float4*>(
                    U + (size_t)lb * 8192 + (size_t)(i0 + it + 2) * 16 + lj4);
            CP_WAIT1();
        } else {
            CP_WAIT0();
        }
        __syncthreads();   // current buffer's W (cp.async) + U (STS) visible

        const float* Wb = Wsb[s];
        const float* Ub = Usb[s];
#pragma unroll
        for (int j = 0; j < 16; j++) {
            const float* wj = Wb + j * 256;
            const float4 w0 = *reinterpret_cast<const float4*>(wj + wc0);
            const float4 w1 = *reinterpret_cast<const float4*>(wj + wc1);
            const float2 wp0 = make_float2(w0.x, w0.y);
            const float2 wp1 = make_float2(w0.z, w0.w);
            const float2 wp2 = make_float2(w1.x, w1.y);
            const float2 wp3 = make_float2(w1.z, w1.w);
            const float* uj = Ub + j * 68;
            const float4 u0 = *reinterpret_cast<const float4*>(uj + uo0);
            const float4 u1 = *reinterpret_cast<const float4*>(uj + uo1);
            const float ub[8] = {u0.x, u0.y, u0.z, u0.w, u1.x, u1.y, u1.z, u1.w};
#pragma unroll
            for (int bb = 0; bb < 8; bb++) {
                const float2 us = make_float2(ub[bb], ub[bb]);
                acc[bb][0] = ffma2(us, wp0, acc[bb][0]);
                acc[bb][1] = ffma2(us, wp1, acc[bb][1]);
                acc[bb][2] = ffma2(us, wp2, acc[bb][2]);
                acc[bb][3] = ffma2(us, wp3, acc[bb][3]);
            }
        }
        s ^= 1;
        __syncthreads();   // everyone done with the just-read buffer
    }

    // flush: thread covers b = bg*8+bb, k = k0+w, l in {lg*4..+3} u {16+lg*4..+3}
#pragma unroll
    for (int bb = 0; bb < 8; bb++) {
        float* dst = g_S + (size_t)(bg * 8 + bb) * KLc + (k0 + w) * 32 + lg * 4;
        atomicAdd(dst + 0,  acc[bb][0].x);
        atomicAdd(dst + 1,  acc[bb][0].y);
        atomicAdd(dst + 2,  acc[bb][1].x);
        atomicAdd(dst + 3,  acc[bb][1].y);
        atomicAdd(dst + 16, acc[bb][2].x);
        atomicAdd(dst + 17, acc[bb][2].y);
        atomicAdd(dst + 18, acc[bb][3].x);
        atomicAdd(dst + 19, acc[bb][3].y);
    }
}

// ---------------------------------------------------------------------------
// Fused pass 2: u_hat in regs -> logits dot S -> softmax -> C-weighted acc.
// Grid (32 i-chunks, 4 b-slices), 512 thr — proven 115.4us config.
// ---------------------------------------------------------------------------
__device__ __forceinline__ int wswz(int c) {
    const int k = c >> 3, lg = (c >> 1) & 3, e = c & 1;
    return ((k >> 1) << 4) | (e << 3) | ((k & 1) << 2) | lg;
}

#define FSM_SS   (2 * 16384)            // after Ws[2][16384]
#define FSM_US   (FSM_SS + 16384)       // Usm[2][256]
#define FSM_ASM  (FSM_US + 512)         // Asm[16][33]
#define FSM_CSM  (FSM_ASM + 16 * 33)    // Csm[16][33]
#define FSM_TOT  (FSM_CSM + 16 * 33)
#define FSM_BYTES (FSM_TOT * 4)         // 202880 B

__device__ __forceinline__ void f_stage_w(const float* __restrict__ Wi,
                                          float* dst, int tx) {
#pragma unroll
    for (int r = 0; r < 8; r++) {
        const int idx = tx + r * 512;          // float4 idx 0..4095
        const int k = idx >> 7, j = (idx >> 3) & 15, lq = idx & 7;
        const int c = k * 8 + lq;
        CP_ASYNC16(smem_u32(dst + j * 1024 + wswz(c) * 4),
                   Wi + (size_t)idx * 4);
    }
}
__device__ __forceinline__ void f_stage_u(const float* __restrict__ U,
                                          float* dst, int b0, int i, int tx) {
    if (tx < 64) {
        const int bb = tx >> 2, j4 = (tx & 3) * 4;
        CP_ASYNC16(smem_u32(dst + bb * 16 + UROT(bb, j4)),
                   U + (size_t)(b0 + bb) * 8192 + (size_t)i * 16 + j4);
    }
}

__global__ void __launch_bounds__(512, 1)
k_fused(const float* __restrict__ U, const float* __restrict__ W) {
    extern __shared__ float sm[];
    float* Ws  = sm;                 // [buf][j][1024 swizzled]
    float* Ss  = sm + FSM_SS;        // [bb][1024 swizzled]
    float* Usm = sm + FSM_US;        // [buf][b*16 + rotated col]
    float* Asm = sm + FSM_ASM;       // [bb][33]
    float* Csm = sm + FSM_CSM;       // [bb][33]

    const int tx = threadIdx.x;
    const int w = tx >> 5;
    const int lane = tx & 31;
    const int bg = lane >> 3;
    const int kk = w * 2 + ((lane >> 2) & 1);
    const int lg = lane & 3;
    const int b0 = blockIdx.y * 16;
    const int i0 = blockIdx.x * FNI;
    const int c0 = ((kk >> 1) << 4) | ((kk & 1) << 2) | lg;
    const int c1 = c0 | 8;

    // stage S slice + first W/U
#pragma unroll
    for (int r = 0; r < 8; r++) {
        const int idx = tx + r * 512;
        const int bb = idx >> 8, c = idx & 255;
        CP_ASYNC16(smem_u32(Ss + bb * 1024 + wswz(c) * 4),
                   g_S + (size_t)(b0 + bb) * KLc + (size_t)c * 4);
    }
    f_stage_w(W + (size_t)i0 * 16384, Ws, tx);
    f_stage_u(U, Usm, b0, i0, tx);
    CP_COMMIT();

    float2 acc[4][4];
#pragma unroll
    for (int bb = 0; bb < 4; bb++)
#pragma unroll
        for (int p = 0; p < 4; p++) acc[bb][p] = make_float2(0.f, 0.f);

    int s = 0;
    for (int it = 0; it < FNI; it++) {
        if (it + 1 < FNI) {
            f_stage_w(W + (size_t)(i0 + it + 1) * 16384, Ws + (s ^ 1) * 16384, tx);
            f_stage_u(U, Usm + (s ^ 1) * 256, b0, i0 + it + 1, tx);
            CP_COMMIT();
            CP_WAIT1();
        } else {
            CP_WAIT0();
        }
        __syncthreads();

        const float* Wb = Ws + s * 16384;
        const float* Ub = Usm + s * 256;

        float2 uh[4][4];
#pragma unroll
        for (int bb = 0; bb < 4; bb++)
#pragma unroll
            for (int p = 0; p < 4; p++) uh[bb][p] = make_float2(0.f, 0.f);
#pragma unroll
        for (int j0 = 0; j0 < 16; j0 += 4) {
            float4 uq[4];
#pragma unroll
            for (int bb = 0; bb < 4; bb++) {
                const int b = bg * 4 + bb;
                uq[bb] = *reinterpret_cast<const float4*>(Ub + b * 16 + UROT(b, j0));
            }
#pragma unroll
            for (int jj = 0; jj < 4; jj++) {
                const float* wj = Wb + (j0 + jj) * 1024;
                const float4 w0 = *reinterpret_cast<const float4*>(wj + c0 * 4);
                const float4 w1 = *reinterpret_cast<const float4*>(wj + c1 * 4);
                const float2 wp0 = make_float2(w0.x, w0.y);
                const float2 wp1 = make_float2(w0.z, w0.w);
                const float2 wp2 = make_float2(w1.x, w1.y);
                const float2 wp3 = make_float2(w1.z, w1.w);
#pragma unroll
                for (int bb = 0; bb < 4; bb++) {
                    const float u = (jj == 0) ? uq[bb].x : (jj == 1) ? uq[bb].y
                                  : (jj == 2) ? uq[bb].z : uq[bb].w;
                    const float2 us = make_float2(u, u);
                    uh[bb][0] = ffma2(us, wp0, uh[bb][0]);
                    uh[bb][1] = ffma2(us, wp1, uh[bb][1]);
                    uh[bb][2] = ffma2(us, wp2, uh[bb][2]);
                    uh[bb][3] = ffma2(us, wp3, uh[bb][3]);
                }
            }
        }

        float a[4];
#pragma unroll
        for (int bb = 0; bb < 4; bb++) {
            const float* sp = Ss + (bg * 4 + bb) * 1024;
            const float4 s0 = *reinterpret_cast<const float4*>(sp + c0 * 4);
            const float4 s1 = *reinterpret_cast<const float4*>(sp + c1 * 4);
            a[bb] = uh[bb][0].x * s0.x + uh[bb][0].y * s0.y
                  + uh[bb][1].x * s0.z + uh[bb][1].y * s0.w
                  + uh[bb][2].x * s1.x + uh[bb][2].y * s1.y
                  + uh[bb][3].x * s1.z + uh[bb][3].y * s1.w;
        }
#pragma unroll
        for (int bb = 0; bb < 4; bb++) {
            a[bb] += __shfl_xor_sync(0xffffffffu, a[bb], 1);
            a[bb] += __shfl_xor_sync(0xffffffffu, a[bb], 2);
        }
        if (lg == 0) {
#pragma unroll
            for (int bb = 0; bb < 4; bb++)
                Asm[(bg * 4 + bb) * 33 + kk] = a[bb];
        }
        __syncthreads();

        {   // softmax: warp w owns b-local row w, lane = k
            const float v = Asm[w * 33 + lane];
            float m = v;
#pragma unroll
            for (int o = 16; o; o >>= 1)
                m = fmaxf(m, __shfl_xor_sync(0xffffffffu, m, o));
            const float ev = __expf((v - m) * INV_SCALE);
            float ssum = ev;
#pragma unroll
            for (int o = 16; o; o >>= 1)
                ssum += __shfl_xor_sync(0xffffffffu, ssum, o);
            Csm[w * 33 + lane] = ev / ssum;
        }
        __syncthreads();

#pragma unroll
        for (int bb = 0; bb < 4; bb++) {
            const float cw = Csm[(bg * 4 + bb) * 33 + kk];
            const float2 cc = make_float2(cw, cw);
#pragma unroll
            for (int p = 0; p < 4; p++)
                acc[bb][p] = ffma2(cc, uh[bb][p], acc[bb][p]);
        }
        s ^= 1;
    }

#pragma unroll
    for (int bb = 0; bb < 4; bb++) {
        float* dst = g_Uh + (size_t)(b0 + bg * 4 + bb) * KLc + kk * 32 + lg * 8;
        atomicAdd(dst + 0, acc[bb][0].x);
        atomicAdd(dst + 1, acc[bb][0].y);
        atomicAdd(dst + 2, acc[bb][1].x);
        atomicAdd(dst + 3, acc[bb][1].y);
        atomicAdd(dst + 4, acc[bb][2].x);
        atomicAdd(dst + 5, acc[bb][2].y);
        atomicAdd(dst + 6, acc[bb][3].x);
        atomicAdd(dst + 7, acc[bb][3].y);
    }
}

// ---------------------------------------------------------------------------
// Squash + scratch re-zero (keeps the zeroed-at-entry invariant).
// ---------------------------------------------------------------------------
__global__ void k_squash(float* __restrict__ out) {
    const int t = blockIdx.x * blockDim.x + threadIdx.x;  // 0..65535
    const float x = g_Uh[t];
    float ss = x * x;
#pragma unroll
    for (int o = 16; o; o >>= 1)
        ss += __shfl_xor_sync(0xffffffffu, ss, o);
    const float n = sqrtf(ss);
    const float coef = (1.f - 1.f / (expf(n) + 1e-20f)) / (n + 1e-20f);
    out[t] = x * coef;
    g_Uh[t] = 0.f;
    g_S[t] = 0.f;
}

// ---------------------------------------------------------------------------
extern "C" void kernel_launch(void* const* d_in, const int* in_sizes, int n_in,
                              void* d_out, int out_size) {
    const float* U = (const float*)d_in[0];
    const float* W = (const float*)d_in[1];
    float* out = (float*)d_out;

    cudaFuncSetAttribute(k_pass1, cudaFuncAttributeMaxDynamicSharedMemorySize,
                         P1_BYTES);
    cudaFuncSetAttribute(k_fused, cudaFuncAttributeMaxDynamicSharedMemorySize,
                         FSM_BYTES);

    k_pass1<<<dim3(4, 32), 256, P1_BYTES>>>(U, W);
    k_fused<<<dim3(32, 4), 512, FSM_BYTES>>>(U, W);
    k_squash<<<256, 256>>>(out);
}

// round 15
// speedup vs baseline: 1.0133x; 1.0133x over previous
#include <cuda_runtime.h>
#include <cstddef>

// Problem: B=64, n_l=512, n_h=32, d_l=16, d_h=32
#define Bsz 64
#define NLc 512
#define NHc 32
#define DLc 16
#define KLc 1024   // NH*DH
#define INV_SCALE 0.17677669529663687f  // 1/sqrt(32)
#define FNI 16     // i's per CTA chunk

// Static scratch (zero-initialized at module load; k_squash re-zeros after use,
// so the "zeroed at entry" invariant is self-restoring across calls/replays).
__device__ float g_S[Bsz * KLc];          // S[b][k*32+l]
__device__ float g_Uh[Bsz * KLc];         // U_h accumulator

// Packed fp32x2 FMA (sm_100+)
__device__ __forceinline__ float2 ffma2(float2 a, float2 b, float2 c) {
    float2 d;
    asm("{\n\t"
        ".reg .b64 ra, rb, rc, rd;\n\t"
        "mov.b64 ra, {%2, %3};\n\t"
        "mov.b64 rb, {%4, %5};\n\t"
        "mov.b64 rc, {%6, %7};\n\t"
        "fma.rn.f32x2 rd, ra, rb, rc;\n\t"
        "mov.b64 {%0, %1}, rd;\n\t"
        "}"
        : "=f"(d.x), "=f"(d.y)
        : "f"(a.x), "f"(a.y), "f"(b.x), "f"(b.y), "f"(c.x), "f"(c.y));
    return d;
}

__device__ __forceinline__ unsigned smem_u32(const void* p) {
    return (unsigned)__cvta_generic_to_shared(p);
}
#define CP_ASYNC16(dst, src) \
    asm volatile("cp.async.ca.shared.global [%0], [%1], 16;" ::"r"(dst), "l"(src))
#define CP_COMMIT() asm volatile("cp.async.commit_group;")
#define CP_WAIT1() asm volatile("cp.async.wait_group 1;" ::: "memory")
#define CP_WAIT0() asm volatile("cp.async.wait_group 0;" ::: "memory")

// U column rotation: store U[b][j] at col ((j + (b & 12)) & 15) -> conflict-free.
#define UROT(b, j) (((j) + ((b) & 12)) & 15)

// ---------------------------------------------------------------------------
// Pass 1 (proven R12 config): S[b][k*32+l] = sum_{i,j} U[b,i*16+j] * W[i,k,j,l]
// Grid (8 k-tiles of 4, 32 i-chunks of 16): W read ONCE. 256 thr, 8 warps.
// ---------------------------------------------------------------------------
#define P1W 2048                        // floats per W buffer (16j x 4k x 32l)
#define P1_FLOATS (2 * P1W + 2 * 1024)  // + U[2][64][16]
#define P1_BYTES (P1_FLOATS * 4)        // 24576 B

__device__ __forceinline__ void p1_stage(const float* __restrict__ U,
                                         const float* __restrict__ W,
                                         int i, int k0, int tx,
                                         float* Ws, float* Us) {
    {   // W tile: 512 float4, two per thread; dst [j][k][l] (transposed)
        const float* Wi = W + (size_t)i * 16384 + (size_t)k0 * 512;
#pragma unroll
        for (int r = 0; r < 2; r++) {
            const int v = tx + r * 256;      // 0..511
            const int k = v >> 7, j = (v >> 3) & 15, lq = v & 7;
            CP_ASYNC16(smem_u32(Ws + j * 128 + k * 32 + lq * 4),
                       Wi + k * 512 + j * 32 + lq * 4);
        }
    }
    {   // U tile: 64x16, one float4 per thread, rotated columns
        const int b = tx >> 2, j4 = (tx & 3) * 4;
        CP_ASYNC16(smem_u32(Us + b * 16 + UROT(b, j4)),
                   U + (size_t)b * 8192 + (size_t)i * 16 + j4);
    }
}

__global__ void __launch_bounds__(256, 2) k_pass1(const float* __restrict__ U,
                                                  const float* __restrict__ W) {
    extern __shared__ float sm[];
    float* Ws  = sm;                 // [2][2048]
    float* Usm = sm + 2 * P1W;       // [2][1024]

    const int tx = threadIdx.x;
    const int w = tx >> 5;
    const int lane = tx & 31;
    const int bg = lane >> 2;            // 8 b-groups of 4 b
    const int lg = lane & 3;             // l quad group
    const int kloc = w & 3;
    const int bhalf = w >> 2;
    const int k0 = blockIdx.x * 4;
    const int i0 = blockIdx.y * FNI;
    const int bbase = bhalf * 32 + bg * 4;
    const int c0 = kloc * 32 + lg * 4;
    const int c1 = c0 + 16;

    float2 acc[4][4];
#pragma unroll
    for (int bb = 0; bb < 4; bb++)
#pragma unroll
        for (int p = 0; p < 4; p++) acc[bb][p] = make_float2(0.f, 0.f);

    p1_stage(U, W, i0, k0, tx, Ws, Usm);
    CP_COMMIT();

    int s = 0;
    for (int it = 0; it < FNI; it++) {
        if (it + 1 < FNI) {
            p1_stage(U, W, i0 + it + 1, k0, tx, Ws + (s ^ 1) * P1W,
                     Usm + (s ^ 1) * 1024);
            CP_COMMIT();
            CP_WAIT1();
        } else {
            CP_WAIT0();
        }
        __syncthreads();

        const float* Wb = Ws + s * P1W;
        const float* Ub = Usm + s * 1024;
#pragma unroll
        for (int j0 = 0; j0 < 16; j0 += 4) {
            float4 uq[4];
#pragma unroll
            for (int bb = 0; bb < 4; bb++) {
                const int b = bbase + bb;
                uq[bb] = *reinterpret_cast<const float4*>(Ub + b * 16 + UROT(b, j0));
            }
#pragma unroll
            for (int jj = 0; jj < 4; jj++) {
                const float* wj = Wb + (j0 + jj) * 128;
                const float4 w0 = *reinterpret_cast<const float4*>(wj + c0);
                const float4 w1 = *reinterpret_cast<const float4*>(wj + c1);
                const float2 wp0 = make_float2(w0.x, w0.y);
                const float2 wp1 = make_float2(w0.z, w0.w);
                const float2 wp2 = make_float2(w1.x, w1.y);
                const float2 wp3 = make_float2(w1.z, w1.w);
#pragma unroll
                for (int bb = 0; bb < 4; bb++) {
                    const float u = (jj == 0) ? uq[bb].x : (jj == 1) ? uq[bb].y
                                  : (jj == 2) ? uq[bb].z : uq[bb].w;
                    const float2 us = make_float2(u, u);
                    acc[bb][0] = ffma2(us, wp0, acc[bb][0]);
                    acc[bb][1] = ffma2(us, wp1, acc[bb][1]);
                    acc[bb][2] = ffma2(us, wp2, acc[bb][2]);
                    acc[bb][3] = ffma2(us, wp3, acc[bb][3]);
                }
            }
        }
        s ^= 1;
        __syncthreads();
    }
#pragma unroll
    for (int bb = 0; bb < 4; bb++) {
        float* dst = g_S + (size_t)(bbase + bb) * KLc + (k0 + kloc) * 32 + lg * 4;
        atomicAdd(dst + 0,  acc[bb][0].x);
        atomicAdd(dst + 1,  acc[bb][0].y);
        atomicAdd(dst + 2,  acc[bb][1].x);
        atomicAdd(dst + 3,  acc[bb][1].y);
        atomicAdd(dst + 16, acc[bb][2].x);
        atomicAdd(dst + 17, acc[bb][2].y);
        atomicAdd(dst + 18, acc[bb][3].x);
        atomicAdd(dst + 19, acc[bb][3].y);
    }
}

// ---------------------------------------------------------------------------
// Fused pass 2: u_hat in regs -> logits dot S(REGISTERS) -> softmax ->
// C-weighted acc. S slice per thread is loop-invariant: 8 float4 in regs.
// Grid (32 i-chunks, 4 b-slices), 512 thr.
// ---------------------------------------------------------------------------
__device__ __forceinline__ int wswz(int c) {
    const int k = c >> 3, lg = (c >> 1) & 3, e = c & 1;
    return ((k >> 1) << 4) | (e << 3) | ((k & 1) << 2) | lg;
}

#define FSM_US   (2 * 16384)            // after Ws[2][16384]
#define FSM_ASM  (FSM_US + 512)         // Asm[16][33]
#define FSM_CSM  (FSM_ASM + 16 * 33)    // Csm[16][33]
#define FSM_TOT  (FSM_CSM + 16 * 33)
#define FSM_BYTES (FSM_TOT * 4)         // 137344 B

__device__ __forceinline__ void f_stage_w(const float* __restrict__ Wi,
                                          float* dst, int tx) {
#pragma unroll
    for (int r = 0; r < 8; r++) {
        const int idx = tx + r * 512;          // float4 idx 0..4095
        const int k = idx >> 7, j = (idx >> 3) & 15, lq = idx & 7;
        const int c = k * 8 + lq;
        CP_ASYNC16(smem_u32(dst + j * 1024 + wswz(c) * 4),
                   Wi + (size_t)idx * 4);
    }
}
__device__ __forceinline__ void f_stage_u(const float* __restrict__ U,
                                          float* dst, int b0, int i, int tx) {
    if (tx < 64) {
        const int bb = tx >> 2, j4 = (tx & 3) * 4;
        CP_ASYNC16(smem_u32(dst + bb * 16 + UROT(bb, j4)),
                   U + (size_t)(b0 + bb) * 8192 + (size_t)i * 16 + j4);
    }
}

__global__ void __launch_bounds__(512, 1)
k_fused(const float* __restrict__ U, const float* __restrict__ W) {
    extern __shared__ float sm[];
    float* Ws  = sm;                 // [buf][j][1024 swizzled]
    float* Usm = sm + FSM_US;        // [buf][b*16 + rotated col]
    float* Asm = sm + FSM_ASM;       // [bb][33]
    float* Csm = sm + FSM_CSM;       // [bb][33]

    const int tx = threadIdx.x;
    const int w = tx >> 5;
    const int lane = tx & 31;
    const int bg = lane >> 3;
    const int kk = w * 2 + ((lane >> 2) & 1);
    const int lg = lane & 3;
    const int b0 = blockIdx.y * 16;
    const int i0 = blockIdx.x * FNI;
    const int c0 = ((kk >> 1) << 4) | ((kk & 1) << 2) | lg;
    const int c1 = c0 | 8;

    // stage first W/U tiles
    f_stage_w(W + (size_t)i0 * 16384, Ws, tx);
    f_stage_u(U, Usm, b0, i0, tx);
    CP_COMMIT();

    // S slice -> registers (loop-invariant): S[b0+bg*4+bb][kk*32 + lg*8 ..+7]
    float4 sr[4][2];
#pragma unroll
    for (int bb = 0; bb < 4; bb++) {
        const float* sp = g_S + (size_t)(b0 + bg * 4 + bb) * KLc + kk * 32 + lg * 8;
        sr[bb][0] = *reinterpret_cast<const float4*>(sp);
        sr[bb][1] = *reinterpret_cast<const float4*>(sp + 4);
    }

    float2 acc[4][4];
#pragma unroll
    for (int bb = 0; bb < 4; bb++)
#pragma unroll
        for (int p = 0; p < 4; p++) acc[bb][p] = make_float2(0.f, 0.f);

    int s = 0;
    for (int it = 0; it < FNI; it++) {
        if (it + 1 < FNI) {
            f_stage_w(W + (size_t)(i0 + it + 1) * 16384, Ws + (s ^ 1) * 16384, tx);
            f_stage_u(U, Usm + (s ^ 1) * 256, b0, i0 + it + 1, tx);
            CP_COMMIT();
            CP_WAIT1();
        } else {
            CP_WAIT0();
        }
        __syncthreads();

        const float* Wb = Ws + s * 16384;
        const float* Ub = Usm + s * 256;

        float2 uh[4][4];
#pragma unroll
        for (int bb = 0; bb < 4; bb++)
#pragma unroll
            for (int p = 0; p < 4; p++) uh[bb][p] = make_float2(0.f, 0.f);
#pragma unroll
        for (int j0 = 0; j0 < 16; j0 += 4) {
            float4 uq[4];
#pragma unroll
            for (int bb = 0; bb < 4; bb++) {
                const int b = bg * 4 + bb;
                uq[bb] = *reinterpret_cast<const float4*>(Ub + b * 16 + UROT(b, j0));
            }
#pragma unroll
            for (int jj = 0; jj < 4; jj++) {
                const float* wj = Wb + (j0 + jj) * 1024;
                const float4 w0 = *reinterpret_cast<const float4*>(wj + c0 * 4);
                const float4 w1 = *reinterpret_cast<const float4*>(wj + c1 * 4);
                const float2 wp0 = make_float2(w0.x, w0.y);
                const float2 wp1 = make_float2(w0.z, w0.w);
                const float2 wp2 = make_float2(w1.x, w1.y);
                const float2 wp3 = make_float2(w1.z, w1.w);
#pragma unroll
                for (int bb = 0; bb < 4; bb++) {
                    const float u = (jj == 0) ? uq[bb].x : (jj == 1) ? uq[bb].y
                                  : (jj == 2) ? uq[bb].z : uq[bb].w;
                    const float2 us = make_float2(u, u);
                    uh[bb][0] = ffma2(us, wp0, uh[bb][0]);
                    uh[bb][1] = ffma2(us, wp1, uh[bb][1]);
                    uh[bb][2] = ffma2(us, wp2, uh[bb][2]);
                    uh[bb][3] = ffma2(us, wp3, uh[bb][3]);
                }
            }
        }

        float a[4];
#pragma unroll
        for (int bb = 0; bb < 4; bb++) {
            a[bb] = uh[bb][0].x * sr[bb][0].x + uh[bb][0].y * sr[bb][0].y
                  + uh[bb][1].x * sr[bb][0].z + uh[bb][1].y * sr[bb][0].w
                  + uh[bb][2].x * sr[bb][1].x + uh[bb][2].y * sr[bb][1].y
                  + uh[bb][3].x * sr[bb][1].z + uh[bb][3].y * sr[bb][1].w;
            a[bb] += __shfl_xor_sync(0xffffffffu, a[bb], 1);
            a[bb] += __shfl_xor_sync(0xffffffffu, a[bb], 2);
        }
        if (lg == 0) {
#pragma unroll
            for (int bb = 0; bb < 4; bb++)
                Asm[(bg * 4 + bb) * 33 + kk] = a[bb];
        }
        __syncthreads();

        {   // softmax: warp w owns b-local row w, lane = k
            const float v = Asm[w * 33 + lane];
            float m = v;
#pragma unroll
            for (int o = 16; o; o >>= 1)
                m = fmaxf(m, __shfl_xor_sync(0xffffffffu, m, o));
            const float ev = __expf((v - m) * INV_SCALE);
            float ssum = ev;
#pragma unroll
            for (int o = 16; o; o >>= 1)
                ssum += __shfl_xor_sync(0xffffffffu, ssum, o);
            Csm[w * 33 + lane] = ev / ssum;
        }
        __syncthreads();

#pragma unroll
        for (int bb = 0; bb < 4; bb++) {
            const float cw = Csm[(bg * 4 + bb) * 33 + kk];
            const float2 cc = make_float2(cw, cw);
#pragma unroll
            for (int p = 0; p < 4; p++)
                acc[bb][p] = ffma2(cc, uh[bb][p], acc[bb][p]);
        }
        s ^= 1;
    }

#pragma unroll
    for (int bb = 0; bb < 4; bb++) {
        float* dst = g_Uh + (size_t)(b0 + bg * 4 + bb) * KLc + kk * 32 + lg * 8;
        atomicAdd(dst + 0, acc[bb][0].x);
        atomicAdd(dst + 1, acc[bb][0].y);
        atomicAdd(dst + 2, acc[bb][1].x);
        atomicAdd(dst + 3, acc[bb][1].y);
        atomicAdd(dst + 4, acc[bb][2].x);
        atomicAdd(dst + 5, acc[bb][2].y);
        atomicAdd(dst + 6, acc[bb][3].x);
        atomicAdd(dst + 7, acc[bb][3].y);
    }
}

// ---------------------------------------------------------------------------
// Squash + scratch re-zero (keeps the zeroed-at-entry invariant).
// ---------------------------------------------------------------------------
__global__ void k_squash(float* __restrict__ out) {
    const int t = blockIdx.x * blockDim.x + threadIdx.x;  // 0..65535
    const float x = g_Uh[t];
    float ss = x * x;
#pragma unroll
    for (int o = 16; o; o >>= 1)
        ss += __shfl_xor_sync(0xffffffffu, ss, o);
    const float n = sqrtf(ss);
    const float coef = (1.f - 1.f / (expf(n) + 1e-20f)) / (n + 1e-20f);
    out[t] = x * coef;
    g_Uh[t] = 0.f;
    g_S[t] = 0.f;
}

// ---------------------------------------------------------------------------
extern "C" void kernel_launch(void* const* d_in, const int* in_sizes, int n_in,
                              void* d_out, int out_size) {
    const float* U = (const float*)d_in[0];
    const float* W = (const float*)d_in[1];
    float* out = (float*)d_out;

    cudaFuncSetAttribute(k_pass1, cudaFuncAttributeMaxDynamicSharedMemorySize,
                         P1_BYTES);
    cudaFuncSetAttribute(k_fused, cudaFuncAttributeMaxDynamicSharedMemorySize,
                         FSM_BYTES);

    k_pass1<<<dim3(8, 32), 256, P1_BYTES>>>(U, W);
    k_fused<<<dim3(32, 4), 512, FSM_BYTES>>>(U, W);
    k_squash<<<256, 256>>>(out);
}

// round 16
// speedup vs baseline: 1.0487x; 1.0350x over previous
#include <cuda_runtime.h>
#include <cstddef>

// Problem: B=64, n_l=512, n_h=32, d_l=16, d_h=32
#define Bsz 64
#define NLc 512
#define NHc 32
#define DLc 16
#define KLc 1024   // NH*DH
#define INV_SCALE 0.17677669529663687f  // 1/sqrt(32)
#define FNI 16     // i's per fused CTA chunk (nominal)
#define FNI_P1 8   // i's per pass1 CTA chunk

// Static scratch (zero-initialized at module load; k_squash re-zeros after use,
// so the "zeroed at entry" invariant is self-restoring across calls/replays).
__device__ float g_S[Bsz * KLc];          // S[b][k*32+l]
__device__ float g_Uh[Bsz * KLc];         // U_h accumulator

// Packed fp32x2 FMA (sm_100+)
__device__ __forceinline__ float2 ffma2(float2 a, float2 b, float2 c) {
    float2 d;
    asm("{\n\t"
        ".reg .b64 ra, rb, rc, rd;\n\t"
        "mov.b64 ra, {%2, %3};\n\t"
        "mov.b64 rb, {%4, %5};\n\t"
        "mov.b64 rc, {%6, %7};\n\t"
        "fma.rn.f32x2 rd, ra, rb, rc;\n\t"
        "mov.b64 {%0, %1}, rd;\n\t"
        "}"
        : "=f"(d.x), "=f"(d.y)
        : "f"(a.x), "f"(a.y), "f"(b.x), "f"(b.y), "f"(c.x), "f"(c.y));
    return d;
}

__device__ __forceinline__ unsigned smem_u32(const void* p) {
    return (unsigned)__cvta_generic_to_shared(p);
}
#define CP_ASYNC16(dst, src) \
    asm volatile("cp.async.ca.shared.global [%0], [%1], 16;" ::"r"(dst), "l"(src))
#define CP_COMMIT() asm volatile("cp.async.commit_group;")
#define CP_WAIT1() asm volatile("cp.async.wait_group 1;" ::: "memory")
#define CP_WAIT0() asm volatile("cp.async.wait_group 0;" ::: "memory")

// U column rotation (fused): conflict-free scalar/vector U reads.
#define UROT(b, j) (((j) + ((b) & 12)) & 15)

// ---------------------------------------------------------------------------
// Pass 1: S[b][k*32+l] = sum_{i,j} U[b,i*16+j] * W[i,k,j,l]
// LDS-halved layout (R14, race-fixed): warp = 1 k, thread tile 8b x 8l,
// U j-major with quad swizzle (2 LDS.128 per j load all 8 U values).
// Grid (4 k-tiles of 8, 64 i-chunks of 8) = 256 CTAs -> 2 CTAs/SM.
// ---------------------------------------------------------------------------
#define P1W 4096                          // W floats per buffer (8k x 16j x 32l)
#define P1U (16 * 68)                     // U floats per buffer [j][68]
#define P1_FLOATS (2 * P1W + 2 * P1U)
#define P1_BYTES (P1_FLOATS * 4)          // 41472 B

// quad swizzle: quad q (of 16 per row) stored at position q ^ ((q>>3)&1)
__device__ __forceinline__ int usig(int q) { return q ^ ((q >> 3) & 1); }

__device__ __forceinline__ void p1_stage_w(const float* __restrict__ W,
                                           int i, int k0, int tx, float* Ws) {
    const float* Wi = W + (size_t)i * 16384 + (size_t)k0 * 512;
#pragma unroll
    for (int r = 0; r < 4; r++) {
        const int v = tx + r * 256;        // float4 idx 0..1023
        const int k = v >> 7, j = (v >> 3) & 15, lq = v & 7;
        CP_ASYNC16(smem_u32(Ws + j * 256 + k * 32 + lq * 4),
                   Wi + (size_t)k * 512 + j * 32 + lq * 4);
    }
}

__global__ void __launch_bounds__(256, 2) k_pass1(const float* __restrict__ U,
                                                  const float* __restrict__ W) {
    extern __shared__ float sm[];
    float* Wsb[2] = {sm, sm + P1W};
    float* Usb[2] = {sm + 2 * P1W, sm + 2 * P1W + P1U};

    const int tx = threadIdx.x;
    const int w = tx >> 5;               // local k
    const int lane = tx & 31;
    const int bg = lane >> 2;            // 8 b-groups of 8 b
    const int lg = lane & 3;             // l quad group
    const int k0 = blockIdx.x * 8;
    const int i0 = blockIdx.y * FNI_P1;
    const int wc0 = w * 32 + lg * 4;     // W chunk e=0 (float offset in j-row)
    const int wc1 = wc0 + 16;            // e=1
    const int uo0 = usig(2 * bg) * 4;    // U chunk offsets within j-row
    const int uo1 = usig(2 * bg + 1) * 4;

    // U loader mapping (LDG->STS staging): (lb, lj4) unique over 256 threads
    const int lb = (tx & 7) + (tx >> 5) * 8;        // b 0..63
    const int lj4 = ((tx >> 3) & 3) * 4;            // j4 in {0,4,8,12}
    const int lsig = usig(lb >> 2) * 4 + (lb & 3);  // storage float offset in row

    float2 acc[8][4];
#pragma unroll
    for (int bb = 0; bb < 8; bb++)
#pragma unroll
        for (int p = 0; p < 4; p++) acc[bb][p] = make_float2(0.f, 0.f);

    // prologue: W(i0) via cp.async; U(i0) direct LDG->STS; prefetch U(i0+1)
    p1_stage_w(W, i0, k0, tx, Wsb[0]);
    CP_COMMIT();
    {
        const float4 u0 = *reinterpret_cast<const float4*>(
            U + (size_t)lb * 8192 + (size_t)i0 * 16 + lj4);
        Usb[0][(lj4 + 0) * 68 + lsig] = u0.x;
        Usb[0][(lj4 + 1) * 68 + lsig] = u0.y;
        Usb[0][(lj4 + 2) * 68 + lsig] = u0.z;
        Usb[0][(lj4 + 3) * 68 + lsig] = u0.w;
    }
    float4 ureg = *reinterpret_cast<const float4*>(
        U + (size_t)lb * 8192 + (size_t)(i0 + 1) * 16 + lj4);

    int s = 0;
    for (int it = 0; it < FNI_P1; it++) {
        // stage next buffer (head of iteration, proven ordering)
        if (it + 1 < FNI_P1) {
            p1_stage_w(W, i0 + it + 1, k0, tx, Wsb[s ^ 1]);
            CP_COMMIT();
            float* Un = Usb[s ^ 1];
            Un[(lj4 + 0) * 68 + lsig] = ureg.x;
            Un[(lj4 + 1) * 68 + lsig] = ureg.y;
            Un[(lj4 + 2) * 68 + lsig] = ureg.z;
            Un[(lj4 + 3) * 68 + lsig] = ureg.w;
            if (it + 2 < FNI_P1)
                ureg = *reinterpret_cast<const float4*>(
                    U + (size_t)lb * 8192 + (size_t)(i0 + it + 2) * 16 + lj4);
            CP_WAIT1();
        } else {
            CP_WAIT0();
        }
        __syncthreads();   // current buffer's W (cp.async) + U (STS) visible

        const float* Wb = Wsb[s];
        const float* Ub = Usb[s];
#pragma unroll
        for (int j = 0; j < 16; j++) {
            const float* wj = Wb + j * 256;
            const float4 w0 = *reinterpret_cast<const float4*>(wj + wc0);
            const float4 w1 = *reinterpret_cast<const float4*>(wj + wc1);
            const float2 wp0 = make_float2(w0.x, w0.y);
            const float2 wp1 = make_float2(w0.z, w0.w);
            const float2 wp2 = make_float2(w1.x, w1.y);
            const float2 wp3 = make_float2(w1.z, w1.w);
            const float* uj = Ub + j * 68;
            const float4 u0 = *reinterpret_cast<const float4*>(uj + uo0);
            const float4 u1 = *reinterpret_cast<const float4*>(uj + uo1);
            const float ub[8] = {u0.x, u0.y, u0.z, u0.w, u1.x, u1.y, u1.z, u1.w};
#pragma unroll
            for (int bb = 0; bb < 8; bb++) {
                const float2 us = make_float2(ub[bb], ub[bb]);
                acc[bb][0] = ffma2(us, wp0, acc[bb][0]);
                acc[bb][1] = ffma2(us, wp1, acc[bb][1]);
                acc[bb][2] = ffma2(us, wp2, acc[bb][2]);
                acc[bb][3] = ffma2(us, wp3, acc[bb][3]);
            }
        }
        s ^= 1;
        __syncthreads();   // everyone done with the just-read buffer
    }

    // flush: thread covers b = bg*8+bb, k = k0+w, l in {lg*4..+3} u {16+lg*4..+3}
#pragma unroll
    for (int bb = 0; bb < 8; bb++) {
        float* dst = g_S + (size_t)(bg * 8 + bb) * KLc + (k0 + w) * 32 + lg * 4;
        atomicAdd(dst + 0,  acc[bb][0].x);
        atomicAdd(dst + 1,  acc[bb][0].y);
        atomicAdd(dst + 2,  acc[bb][1].x);
        atomicAdd(dst + 3,  acc[bb][1].y);
        atomicAdd(dst + 16, acc[bb][2].x);
        atomicAdd(dst + 17, acc[bb][2].y);
        atomicAdd(dst + 18, acc[bb][3].x);
        atomicAdd(dst + 19, acc[bb][3].y);
    }
}

// ---------------------------------------------------------------------------
// Fused pass 2: u_hat in regs -> logits dot S(regs) -> softmax -> C-weighted
// acc. Balanced grid (37 i-splits x 4 b-slices) = 148 CTAs = 1 full wave.
// ---------------------------------------------------------------------------
__device__ __forceinline__ int wswz(int c) {
    const int k = c >> 3, lg = (c >> 1) & 3, e = c & 1;
    return ((k >> 1) << 4) | (e << 3) | ((k & 1) << 2) | lg;
}

#define FSM_US   (2 * 16384)            // after Ws[2][16384]
#define FSM_ASM  (FSM_US + 512)         // Asm[16][33]
#define FSM_CSM  (FSM_ASM + 16 * 33)    // Csm[16][33]
#define FSM_TOT  (FSM_CSM + 16 * 33)
#define FSM_BYTES (FSM_TOT * 4)         // 137344 B

__device__ __forceinline__ void f_stage_w(const float* __restrict__ Wi,
                                          float* dst, int tx) {
#pragma unroll
    for (int r = 0; r < 8; r++) {
        const int idx = tx + r * 512;          // float4 idx 0..4095
        const int k = idx >> 7, j = (idx >> 3) & 15, lq = idx & 7;
        const int c = k * 8 + lq;
        CP_ASYNC16(smem_u32(dst + j * 1024 + wswz(c) * 4),
                   Wi + (size_t)idx * 4);
    }
}
__device__ __forceinline__ void f_stage_u(const float* __restrict__ U,
                                          float* dst, int b0, int i, int tx) {
    if (tx < 64) {
        const int bb = tx >> 2, j4 = (tx & 3) * 4;
        CP_ASYNC16(smem_u32(dst + bb * 16 + UROT(bb, j4)),
                   U + (size_t)(b0 + bb) * 8192 + (size_t)i * 16 + j4);
    }
}

__global__ void __launch_bounds__(512, 1)
k_fused(const float* __restrict__ U, const float* __restrict__ W) {
    extern __shared__ float sm[];
    float* Ws  = sm;                 // [buf][j][1024 swizzled]
    float* Usm = sm + FSM_US;        // [buf][b*16 + rotated col]
    float* Asm = sm + FSM_ASM;       // [bb][33]
    float* Csm = sm + FSM_CSM;       // [bb][33]

    const int tx = threadIdx.x;
    const int w = tx >> 5;
    const int lane = tx & 31;
    const int bg = lane >> 3;
    const int kk = w * 2 + ((lane >> 2) & 1);
    const int lg = lane & 3;
    const int b0 = blockIdx.y * 16;
    // balanced i-range: chunk c covers [c*512/37, (c+1)*512/37)
    const int i0 = (blockIdx.x * NLc) / 37;
    const int ni = ((blockIdx.x + 1) * NLc) / 37 - i0;
    const int c0 = ((kk >> 1) << 4) | ((kk & 1) << 2) | lg;
    const int c1 = c0 | 8;

    // stage first W/U tiles
    f_stage_w(W + (size_t)i0 * 16384, Ws, tx);
    f_stage_u(U, Usm, b0, i0, tx);
    CP_COMMIT();

    // S slice -> registers (loop-invariant)
    float4 sr[4][2];
#pragma unroll
    for (int bb = 0; bb < 4; bb++) {
        const float* sp = g_S + (size_t)(b0 + bg * 4 + bb) * KLc + kk * 32 + lg * 8;
        sr[bb][0] = *reinterpret_cast<const float4*>(sp);
        sr[bb][1] = *reinterpret_cast<const float4*>(sp + 4);
    }

    float2 acc[4][4];
#pragma unroll
    for (int bb = 0; bb < 4; bb++)
#pragma unroll
        for (int p = 0; p < 4; p++) acc[bb][p] = make_float2(0.f, 0.f);

    int s = 0;
    for (int it = 0; it < ni; it++) {
        if (it + 1 < ni) {
            f_stage_w(W + (size_t)(i0 + it + 1) * 16384, Ws + (s ^ 1) * 16384, tx);
            f_stage_u(U, Usm + (s ^ 1) * 256, b0, i0 + it + 1, tx);
            CP_COMMIT();
            CP_WAIT1();
        } else {
            CP_WAIT0();
        }
        __syncthreads();

        const float* Wb = Ws + s * 16384;
        const float* Ub = Usm + s * 256;

        float2 uh[4][4];
#pragma unroll
        for (int bb = 0; bb < 4; bb++)
#pragma unroll
            for (int p = 0; p < 4; p++) uh[bb][p] = make_float2(0.f, 0.f);
#pragma unroll
        for (int j0 = 0; j0 < 16; j0 += 4) {
            float4 uq[4];
#pragma unroll
            for (int bb = 0; bb < 4; bb++) {
                const int b = bg * 4 + bb;
                uq[bb] = *reinterpret_cast<const float4*>(Ub + b * 16 + UROT(b, j0));
            }
#pragma unroll
            for (int jj = 0; jj < 4; jj++) {
                const float* wj = Wb + (j0 + jj) * 1024;
                const float4 w0 = *reinterpret_cast<const float4*>(wj + c0 * 4);
                const float4 w1 = *reinterpret_cast<const float4*>(wj + c1 * 4);
                const float2 wp0 = make_float2(w0.x, w0.y);
                const float2 wp1 = make_float2(w0.z, w0.w);
                const float2 wp2 = make_float2(w1.x, w1.y);
                const float2 wp3 = make_float2(w1.z, w1.w);
#pragma unroll
                for (int bb = 0; bb < 4; bb++) {
                    const float u = (jj == 0) ? uq[bb].x : (jj == 1) ? uq[bb].y
                                  : (jj == 2) ? uq[bb].z : uq[bb].w;
                    const float2 us = make_float2(u, u);
                    uh[bb][0] = ffma2(us, wp0, uh[bb][0]);
                    uh[bb][1] = ffma2(us, wp1, uh[bb][1]);
                    uh[bb][2] = ffma2(us, wp2, uh[bb][2]);
                    uh[bb][3] = ffma2(us, wp3, uh[bb][3]);
                }
            }
        }

        float a[4];
#pragma unroll
        for (int bb = 0; bb < 4; bb++) {
            a[bb] = uh[bb][0].x * sr[bb][0].x + uh[bb][0].y * sr[bb][0].y
                  + uh[bb][1].x * sr[bb][0].z + uh[bb][1].y * sr[bb][0].w
                  + uh[bb][2].x * sr[bb][1].x + uh[bb][2].y * sr[bb][1].y
                  + uh[bb][3].x * sr[bb][1].z + uh[bb][3].y * sr[bb][1].w;
            a[bb] += __shfl_xor_sync(0xffffffffu, a[bb], 1);
            a[bb] += __shfl_xor_sync(0xffffffffu, a[bb], 2);
        }
        if (lg == 0) {
#pragma unroll
            for (int bb = 0; bb < 4; bb++)
                Asm[(bg * 4 + bb) * 33 + kk] = a[bb];
        }
        __syncthreads();

        {   // softmax: warp w owns b-local row w, lane = k
            const float v = Asm[w * 33 + lane];
            float m = v;
#pragma unroll
            for (int o = 16; o; o >>= 1)
                m = fmaxf(m, __shfl_xor_sync(0xffffffffu, m, o));
            const float ev = __expf((v - m) * INV_SCALE);
            float ssum = ev;
#pragma unroll
            for (int o = 16; o; o >>= 1)
                ssum += __shfl_xor_sync(0xffffffffu, ssum, o);
            Csm[w * 33 + lane] = ev / ssum;
        }
        __syncthreads();

#pragma unroll
        for (int bb = 0; bb < 4; bb++) {
            const float cw = Csm[(bg * 4 + bb) * 33 + kk];
            const float2 cc = make_float2(cw, cw);
#pragma unroll
            for (int p = 0; p < 4; p++)
                acc[bb][p] = ffma2(cc, uh[bb][p], acc[bb][p]);
        }
        s ^= 1;
    }

#pragma unroll
    for (int bb = 0; bb < 4; bb++) {
        float* dst = g_Uh + (size_t)(b0 + bg * 4 + bb) * KLc + kk * 32 + lg * 8;
        atomicAdd(dst + 0, acc[bb][0].x);
        atomicAdd(dst + 1, acc[bb][0].y);
        atomicAdd(dst + 2, acc[bb][1].x);
        atomicAdd(dst + 3, acc[bb][1].y);
        atomicAdd(dst + 4, acc[bb][2].x);
        atomicAdd(dst + 5, acc[bb][2].y);
        atomicAdd(dst + 6, acc[bb][3].x);
        atomicAdd(dst + 7, acc[bb][3].y);
    }
}

// ---------------------------------------------------------------------------
// Squash + scratch re-zero (keeps the zeroed-at-entry invariant).
// ---------------------------------------------------------------------------
__global__ void k_squash(float* __restrict__ out) {
    const int t = blockIdx.x * blockDim.x + threadIdx.x;  // 0..65535
    const float x = g_Uh[t];
    float ss = x * x;
#pragma unroll
    for (int o = 16; o; o >>= 1)
        ss += __shfl_xor_sync(0xffffffffu, ss, o);
    const float n = sqrtf(ss);
    const float coef = (1.f - 1.f / (expf(n) + 1e-20f)) / (n + 1e-20f);
    out[t] = x * coef;
    g_Uh[t] = 0.f;
    g_S[t] = 0.f;
}

// ---------------------------------------------------------------------------
extern "C" void kernel_launch(void* const* d_in, const int* in_sizes, int n_in,
                              void* d_out, int out_size) {
    const float* U = (const float*)d_in[0];
    const float* W = (const float*)d_in[1];
    float* out = (float*)d_out;

    cudaFuncSetAttribute(k_pass1, cudaFuncAttributeMaxDynamicSharedMemorySize,
                         P1_BYTES);
    cudaFuncSetAttribute(k_fused, cudaFuncAttributeMaxDynamicSharedMemorySize,
                         FSM_BYTES);

    k_pass1<<<dim3(4, 64), 256, P1_BYTES>>>(U, W);
    k_fused<<<dim3(37, 4), 512, FSM_BYTES>>>(U, W);
    k_squash<<<256, 256>>>(out);
}

// round 17
// speedup vs baseline: 1.0755x; 1.0256x over previous
#include <cuda_runtime.h>
#include <cstddef>

// Problem: B=64, n_l=512, n_h=32, d_l=16, d_h=32
#define Bsz 64
#define NLc 512
#define NHc 32
#define DLc 16
#define KLc 1024   // NH*DH
#define INV_SCALE 0.17677669529663687f  // 1/sqrt(32)
#define FNI 16     // i's per pass1 CTA chunk

// Static scratch (zero-initialized at module load; k_squash re-zeros after use,
// so the "zeroed at entry" invariant is self-restoring across calls/replays).
__device__ float g_S[Bsz * KLc];          // S[b][k*32+l]
__device__ float g_Uh[Bsz * KLc];         // U_h accumulator

// Packed fp32x2 FMA (sm_100+)
__device__ __forceinline__ float2 ffma2(float2 a, float2 b, float2 c) {
    float2 d;
    asm("{\n\t"
        ".reg .b64 ra, rb, rc, rd;\n\t"
        "mov.b64 ra, {%2, %3};\n\t"
        "mov.b64 rb, {%4, %5};\n\t"
        "mov.b64 rc, {%6, %7};\n\t"
        "fma.rn.f32x2 rd, ra, rb, rc;\n\t"
        "mov.b64 {%0, %1}, rd;\n\t"
        "}"
        : "=f"(d.x), "=f"(d.y)
        : "f"(a.x), "f"(a.y), "f"(b.x), "f"(b.y), "f"(c.x), "f"(c.y));
    return d;
}

__device__ __forceinline__ unsigned smem_u32(const void* p) {
    return (unsigned)__cvta_generic_to_shared(p);
}
#define CP_ASYNC16(dst, src) \
    asm volatile("cp.async.ca.shared.global [%0], [%1], 16;" ::"r"(dst), "l"(src))
#define CP_COMMIT() asm volatile("cp.async.commit_group;")
#define CP_WAIT1() asm volatile("cp.async.wait_group 1;" ::: "memory")
#define CP_WAIT0() asm volatile("cp.async.wait_group 0;" ::: "memory")

// U column rotation: store U[b][j] at col ((j + (b & 12)) & 15) -> conflict-free.
#define UROT(b, j) (((j) + ((b) & 12)) & 15)

// ---------------------------------------------------------------------------
// Pass 1 (proven R12 config, 37.2us): S[b][k*32+l] = sum_{i,j} U*W
// Grid (8 k-tiles of 4, 32 i-chunks of 16): W read ONCE. 256 thr, 8 warps.
// ---------------------------------------------------------------------------
#define P1W 2048                        // floats per W buffer (16j x 4k x 32l)
#define P1_FLOATS (2 * P1W + 2 * 1024)  // + U[2][64][16]
#define P1_BYTES (P1_FLOATS * 4)        // 24576 B

__device__ __forceinline__ void p1_stage(const float* __restrict__ U,
                                         const float* __restrict__ W,
                                         int i, int k0, int tx,
                                         float* Ws, float* Us) {
    {   // W tile: 512 float4, two per thread; dst [j][k][l] (transposed)
        const float* Wi = W + (size_t)i * 16384 + (size_t)k0 * 512;
#pragma unroll
        for (int r = 0; r < 2; r++) {
            const int v = tx + r * 256;      // 0..511
            const int k = v >> 7, j = (v >> 3) & 15, lq = v & 7;
            CP_ASYNC16(smem_u32(Ws + j * 128 + k * 32 + lq * 4),
                       Wi + k * 512 + j * 32 + lq * 4);
        }
    }
    {   // U tile: 64x16, one float4 per thread, rotated columns
        const int b = tx >> 2, j4 = (tx & 3) * 4;
        CP_ASYNC16(smem_u32(Us + b * 16 + UROT(b, j4)),
                   U + (size_t)b * 8192 + (size_t)i * 16 + j4);
    }
}

__global__ void __launch_bounds__(256, 2) k_pass1(const float* __restrict__ U,
                                                  const float* __restrict__ W) {
    extern __shared__ float sm[];
    float* Ws  = sm;                 // [2][2048]
    float* Usm = sm + 2 * P1W;       // [2][1024]

    const int tx = threadIdx.x;
    const int w = tx >> 5;
    const int lane = tx & 31;
    const int bg = lane >> 2;            // 8 b-groups of 4 b
    const int lg = lane & 3;             // l quad group
    const int kloc = w & 3;
    const int bhalf = w >> 2;
    const int k0 = blockIdx.x * 4;
    const int i0 = blockIdx.y * FNI;
    const int bbase = bhalf * 32 + bg * 4;
    const int c0 = kloc * 32 + lg * 4;
    const int c1 = c0 + 16;

    float2 acc[4][4];
#pragma unroll
    for (int bb = 0; bb < 4; bb++)
#pragma unroll
        for (int p = 0; p < 4; p++) acc[bb][p] = make_float2(0.f, 0.f);

    p1_stage(U, W, i0, k0, tx, Ws, Usm);
    CP_COMMIT();

    int s = 0;
    for (int it = 0; it < FNI; it++) {
        if (it + 1 < FNI) {
            p1_stage(U, W, i0 + it + 1, k0, tx, Ws + (s ^ 1) * P1W,
                     Usm + (s ^ 1) * 1024);
            CP_COMMIT();
            CP_WAIT1();
        } else {
            CP_WAIT0();
        }
        __syncthreads();

        const float* Wb = Ws + s * P1W;
        const float* Ub = Usm + s * 1024;
#pragma unroll
        for (int j0 = 0; j0 < 16; j0 += 4) {
            float4 uq[4];
#pragma unroll
            for (int bb = 0; bb < 4; bb++) {
                const int b = bbase + bb;
                uq[bb] = *reinterpret_cast<const float4*>(Ub + b * 16 + UROT(b, j0));
            }
#pragma unroll
            for (int jj = 0; jj < 4; jj++) {
                const float* wj = Wb + (j0 + jj) * 128;
                const float4 w0 = *reinterpret_cast<const float4*>(wj + c0);
                const float4 w1 = *reinterpret_cast<const float4*>(wj + c1);
                const float2 wp0 = make_float2(w0.x, w0.y);
                const float2 wp1 = make_float2(w0.z, w0.w);
                const float2 wp2 = make_float2(w1.x, w1.y);
                const float2 wp3 = make_float2(w1.z, w1.w);
#pragma unroll
                for (int bb = 0; bb < 4; bb++) {
                    const float u = (jj == 0) ? uq[bb].x : (jj == 1) ? uq[bb].y
                                  : (jj == 2) ? uq[bb].z : uq[bb].w;
                    const float2 us = make_float2(u, u);
                    acc[bb][0] = ffma2(us, wp0, acc[bb][0]);
                    acc[bb][1] = ffma2(us, wp1, acc[bb][1]);
                    acc[bb][2] = ffma2(us, wp2, acc[bb][2]);
                    acc[bb][3] = ffma2(us, wp3, acc[bb][3]);
                }
            }
        }
        s ^= 1;
        __syncthreads();
    }
#pragma unroll
    for (int bb = 0; bb < 4; bb++) {
        float* dst = g_S + (size_t)(bbase + bb) * KLc + (k0 + kloc) * 32 + lg * 4;
        atomicAdd(dst + 0,  acc[bb][0].x);
        atomicAdd(dst + 1,  acc[bb][0].y);
        atomicAdd(dst + 2,  acc[bb][1].x);
        atomicAdd(dst + 3,  acc[bb][1].y);
        atomicAdd(dst + 16, acc[bb][2].x);
        atomicAdd(dst + 17, acc[bb][2].y);
        atomicAdd(dst + 18, acc[bb][3].x);
        atomicAdd(dst + 19, acc[bb][3].y);
    }
}

// ---------------------------------------------------------------------------
// Fused pass 2 (proven R16 config): u_hat in regs -> logits dot S(regs) ->
// softmax -> C-weighted acc. Balanced grid (37 x 4) = 148 CTAs = 1 wave.
// ---------------------------------------------------------------------------
__device__ __forceinline__ int wswz(int c) {
    const int k = c >> 3, lg = (c >> 1) & 3, e = c & 1;
    return ((k >> 1) << 4) | (e << 3) | ((k & 1) << 2) | lg;
}

#define FSM_US   (2 * 16384)            // after Ws[2][16384]
#define FSM_ASM  (FSM_US + 512)         // Asm[16][33]
#define FSM_CSM  (FSM_ASM + 16 * 33)    // Csm[16][33]
#define FSM_TOT  (FSM_CSM + 16 * 33)
#define FSM_BYTES (FSM_TOT * 4)         // 137344 B

__device__ __forceinline__ void f_stage_w(const float* __restrict__ Wi,
                                          float* dst, int tx) {
#pragma unroll
    for (int r = 0; r < 8; r++) {
        const int idx = tx + r * 512;          // float4 idx 0..4095
        const int k = idx >> 7, j = (idx >> 3) & 15, lq = idx & 7;
        const int c = k * 8 + lq;
        CP_ASYNC16(smem_u32(dst + j * 1024 + wswz(c) * 4),
                   Wi + (size_t)idx * 4);
    }
}
__device__ __forceinline__ void f_stage_u(const float* __restrict__ U,
                                          float* dst, int b0, int i, int tx) {
    if (tx < 64) {
        const int bb = tx >> 2, j4 = (tx & 3) * 4;
        CP_ASYNC16(smem_u32(dst + bb * 16 + UROT(bb, j4)),
                   U + (size_t)(b0 + bb) * 8192 + (size_t)i * 16 + j4);
    }
}

__global__ void __launch_bounds__(512, 1)
k_fused(const float* __restrict__ U, const float* __restrict__ W) {
    extern __shared__ float sm[];
    float* Ws  = sm;                 // [buf][j][1024 swizzled]
    float* Usm = sm + FSM_US;        // [buf][b*16 + rotated col]
    float* Asm = sm + FSM_ASM;       // [bb][33]
    float* Csm = sm + FSM_CSM;       // [bb][33]

    const int tx = threadIdx.x;
    const int w = tx >> 5;
    const int lane = tx & 31;
    const int bg = lane >> 3;
    const int kk = w * 2 + ((lane >> 2) & 1);
    const int lg = lane & 3;
    const int b0 = blockIdx.y * 16;
    // balanced i-range: chunk c covers [c*512/37, (c+1)*512/37)
    const int i0 = (blockIdx.x * NLc) / 37;
    const int ni = ((blockIdx.x + 1) * NLc) / 37 - i0;
    const int c0 = ((kk >> 1) << 4) | ((kk & 1) << 2) | lg;
    const int c1 = c0 | 8;

    // stage first W/U tiles
    f_stage_w(W + (size_t)i0 * 16384, Ws, tx);
    f_stage_u(U, Usm, b0, i0, tx);
    CP_COMMIT();

    // S slice -> registers (loop-invariant)
    float4 sr[4][2];
#pragma unroll
    for (int bb = 0; bb < 4; bb++) {
        const float* sp = g_S + (size_t)(b0 + bg * 4 + bb) * KLc + kk * 32 + lg * 8;
        sr[bb][0] = *reinterpret_cast<const float4*>(sp);
        sr[bb][1] = *reinterpret_cast<const float4*>(sp + 4);
    }

    float2 acc[4][4];
#pragma unroll
    for (int bb = 0; bb < 4; bb++)
#pragma unroll
        for (int p = 0; p < 4; p++) acc[bb][p] = make_float2(0.f, 0.f);

    int s = 0;
    for (int it = 0; it < ni; it++) {
        if (it + 1 < ni) {
            f_stage_w(W + (size_t)(i0 + it + 1) * 16384, Ws + (s ^ 1) * 16384, tx);
            f_stage_u(U, Usm + (s ^ 1) * 256, b0, i0 + it + 1, tx);
            CP_COMMIT();
            CP_WAIT1();
        } else {
            CP_WAIT0();
        }
        __syncthreads();

        const float* Wb = Ws + s * 16384;
        const float* Ub = Usm + s * 256;

        float2 uh[4][4];
#pragma unroll
        for (int bb = 0; bb < 4; bb++)
#pragma unroll
            for (int p = 0; p < 4; p++) uh[bb][p] = make_float2(0.f, 0.f);
#pragma unroll
        for (int j0 = 0; j0 < 16; j0 += 4) {
            float4 uq[4];
#pragma unroll
            for (int bb = 0; bb < 4; bb++) {
                const int b = bg * 4 + bb;
                uq[bb] = *reinterpret_cast<const float4*>(Ub + b * 16 + UROT(b, j0));
            }
#pragma unroll
            for (int jj = 0; jj < 4; jj++) {
                const float* wj = Wb + (j0 + jj) * 1024;
                const float4 w0 = *reinterpret_cast<const float4*>(wj + c0 * 4);
                const float4 w1 = *reinterpret_cast<const float4*>(wj + c1 * 4);
                const float2 wp0 = make_float2(w0.x, w0.y);
                const float2 wp1 = make_float2(w0.z, w0.w);
                const float2 wp2 = make_float2(w1.x, w1.y);
                const float2 wp3 = make_float2(w1.z, w1.w);
#pragma unroll
                for (int bb = 0; bb < 4; bb++) {
                    const float u = (jj == 0) ? uq[bb].x : (jj == 1) ? uq[bb].y
                                  : (jj == 2) ? uq[bb].z : uq[bb].w;
                    const float2 us = make_float2(u, u);
                    uh[bb][0] = ffma2(us, wp0, uh[bb][0]);
                    uh[bb][1] = ffma2(us, wp1, uh[bb][1]);
                    uh[bb][2] = ffma2(us, wp2, uh[bb][2]);
                    uh[bb][3] = ffma2(us, wp3, uh[bb][3]);
                }
            }
        }

        float a[4];
#pragma unroll
        for (int bb = 0; bb < 4; bb++) {
            a[bb] = uh[bb][0].x * sr[bb][0].x + uh[bb][0].y * sr[bb][0].y
                  + uh[bb][1].x * sr[bb][0].z + uh[bb][1].y * sr[bb][0].w
                  + uh[bb][2].x * sr[bb][1].x + uh[bb][2].y * sr[bb][1].y
                  + uh[bb][3].x * sr[bb][1].z + uh[bb][3].y * sr[bb][1].w;
            a[bb] += __shfl_xor_sync(0xffffffffu, a[bb], 1);
            a[bb] += __shfl_xor_sync(0xffffffffu, a[bb], 2);
        }
        if (lg == 0) {
#pragma unroll
            for (int bb = 0; bb < 4; bb++)
                Asm[(bg * 4 + bb) * 33 + kk] = a[bb];
        }
        __syncthreads();

        {   // softmax: warp w owns b-local row w, lane = k
            const float v = Asm[w * 33 + lane];
            float m = v;
#pragma unroll
            for (int o = 16; o; o >>= 1)
                m = fmaxf(m, __shfl_xor_sync(0xffffffffu, m, o));
            const float ev = __expf((v - m) * INV_SCALE);
            float ssum = ev;
#pragma unroll
            for (int o = 16; o; o >>= 1)
                ssum += __shfl_xor_sync(0xffffffffu, ssum, o);
            Csm[w * 33 + lane] = ev / ssum;
        }
        __syncthreads();

#pragma unroll
        for (int bb = 0; bb < 4; bb++) {
            const float cw = Csm[(bg * 4 + bb) * 33 + kk];
            const float2 cc = make_float2(cw, cw);
#pragma unroll
            for (int p = 0; p < 4; p++)
                acc[bb][p] = ffma2(cc, uh[bb][p], acc[bb][p]);
        }
        s ^= 1;
    }

#pragma unroll
    for (int bb = 0; bb < 4; bb++) {
        float* dst = g_Uh + (size_t)(b0 + bg * 4 + bb) * KLc + kk * 32 + lg * 8;
        atomicAdd(dst + 0, acc[bb][0].x);
        atomicAdd(dst + 1, acc[bb][0].y);
        atomicAdd(dst + 2, acc[bb][1].x);
        atomicAdd(dst + 3, acc[bb][1].y);
        atomicAdd(dst + 4, acc[bb][2].x);
        atomicAdd(dst + 5, acc[bb][2].y);
        atomicAdd(dst + 6, acc[bb][3].x);
        atomicAdd(dst + 7, acc[bb][3].y);
    }
}

// ---------------------------------------------------------------------------
// Squash + scratch re-zero (keeps the zeroed-at-entry invariant).
// ---------------------------------------------------------------------------
__global__ void k_squash(float* __restrict__ out) {
    const int t = blockIdx.x * blockDim.x + threadIdx.x;  // 0..65535
    const float x = g_Uh[t];
    float ss = x * x;
#pragma unroll
    for (int o = 16; o; o >>= 1)
        ss += __shfl_xor_sync(0xffffffffu, ss, o);
    const float n = sqrtf(ss);
    const float coef = (1.f - 1.f / (expf(n) + 1e-20f)) / (n + 1e-20f);
    out[t] = x * coef;
    g_Uh[t] = 0.f;
    g_S[t] = 0.f;
}

// ---------------------------------------------------------------------------
extern "C" void kernel_launch(void* const* d_in, const int* in_sizes, int n_in,
                              void* d_out, int out_size) {
    const float* U = (const float*)d_in[0];
    const float* W = (const float*)d_in[1];
    float* out = (float*)d_out;

    cudaFuncSetAttribute(k_pass1, cudaFuncAttributeMaxDynamicSharedMemorySize,
                         P1_BYTES);
    cudaFuncSetAttribute(k_fused, cudaFuncAttributeMaxDynamicSharedMemorySize,
                         FSM_BYTES);

    k_pass1<<<dim3(8, 32), 256, P1_BYTES>>>(U, W);
    k_fused<<<dim3(37, 4), 512, FSM_BYTES>>>(U, W);
    k_squash<<<256, 256>>>(out);
}